// round 17
// baseline (speedup 1.0000x reference)
#include <cuda_runtime.h>
#include <cuda_fp16.h>
#include <mma.h>
#include <cstdint>
#include <cstddef>

using namespace nvcuda;

// Shapes: x[8,256,128,128] f32, kpts[8,4096,2], W[128,256], b[128] -> out[8,4096,128] f32
#define NB 8
#define NC 256
#define NPIX 16384
#define NE 128
#define NPTS 4096
#define NTILES 1024           // NB * NPIX/128
#define GRID1 296             // 2 CTAs per SM
#define NTHR 256

// SMEM geometry (half elements). Row strides = 16 mod 128 bytes.
#define WLDH 264              // W row stride (528B)
#define PLDH 136              // X row stride (272B)
#define SM_W_OFF 0
#define SM_X_OFF (128 * WLDH * 2)                 // 67584
#define XBUF_B   (64 * PLDH * 2)                  // 17408 per buffer
#define SM_TOT   (SM_X_OFF + 2 * XBUF_B)          // 102400 B -> 2 CTAs/SM
#define STLD 66               // epilogue stage row stride (floats)

// Scratch: Wx[b, pixel, e] fp16 (32 MiB). Bias added later in k2 (fp32).
__device__ __half g_wxh[(size_t)NB * NPIX * NE];

// ===== Kernel 1: Wx[b,pix,e] = sum_c W[e,c] * x[b,c,pix]  (single-term fp16 WMMA) =====
__global__ void __launch_bounds__(NTHR, 2) k1_whiten(const float* __restrict__ x,
                                                     const float* __restrict__ wmat) {
    extern __shared__ char smem[];
    __half* Ws = (__half*)(smem + SM_W_OFF);
    __half* Xb[2] = { (__half*)(smem + SM_X_OFF), (__half*)(smem + SM_X_OFF + XBUF_B) };

    const int tid = threadIdx.x;
    const int wid = tid >> 5;
    const int lane = tid & 31;
    const int wm = wid & 3;          // pixel sub-tile (32 rows)
    const int wn = wid >> 2;         // E sub-tile (64 cols)

    // staging registers: 8 float4/thread = one 64ch x 128pix chunk per CTA
    float4 v[8];
#define LOAD_CHUNK(Tv, ck)                                                           \
    do {                                                                             \
        const float* xb_ = x + (size_t)((Tv) >> 7) * NC * NPIX + (((Tv) & 127) << 7) \
                         + (size_t)(ck) * 64 * NPIX;                                 \
        _Pragma("unroll")                                                            \
        for (int j = 0; j < 8; j++) {                                                \
            int q = j * NTHR + tid;                                                  \
            v[j] = ((const float4*)(xb_ + (size_t)(q >> 5) * NPIX))[q & 31];         \
        }                                                                            \
    } while (0)

    LOAD_CHUNK(blockIdx.x, 0);   // overlap first chunk load with W prologue

    // ---- W prologue: [128 E][256 c] -> fp16, row stride WLDH ----
    for (int q = tid; q < 16384; q += NTHR) {
        int e = q >> 7, c2 = q & 127;
        float2 w = *(const float2*)(wmat + e * 256 + c2 * 2);
        *(__half2*)(Ws + e * WLDH + c2 * 2) = __floats2half2_rn(w.x, w.y);
    }

    for (int T = blockIdx.x; T < NTILES; T += GRID1) {
        const int b = T >> 7;
        const int pix0 = (T & 127) << 7;

        wmma::fragment<wmma::accumulator, 16, 16, 16, float> acc[2][4];
#pragma unroll
        for (int mi = 0; mi < 2; mi++)
#pragma unroll
            for (int ni = 0; ni < 4; ni++)
                wmma::fill_fragment(acc[mi][ni], 0.0f);

#pragma unroll
        for (int c = 0; c < 4; c++) {            // 4 chunks of 64 channels
            __half* Xc = Xb[c & 1];
            // ---- STS staged chunk: channel-major fp16, contiguous 8B stores ----
#pragma unroll
            for (int j = 0; j < 8; j++) {
                int q = j * NTHR + tid;
                int ch = q >> 5, p4 = q & 31;
                float4 t = v[j];
                __half2 h0 = __floats2half2_rn(t.x, t.y);
                __half2 h1 = __floats2half2_rn(t.z, t.w);
                *(uint2*)(Xc + ch * PLDH + p4 * 4) =
                    make_uint2(*(uint32_t*)&h0, *(uint32_t*)&h1);
            }
            __syncthreads();

            // ---- prefetch next chunk into regs (overlaps with MMA below) ----
            {
                int nT = (c == 3) ? T + GRID1 : T;
                int nc = (c == 3) ? 0 : c + 1;
                if (nT < NTILES) LOAD_CHUNK(nT, nc);
            }

            // ---- MMA over this chunk: 4 k-steps of 16 ----
#pragma unroll
            for (int ks = 0; ks < 4; ks++) {
                const int kb = ks * 16;              // channel offset within chunk
                const int kg = c * 64 + kb;          // global channel (for W)
                wmma::fragment<wmma::matrix_a, 16, 16, 16, __half, wmma::col_major> a[2];
#pragma unroll
                for (int mi = 0; mi < 2; mi++)
                    wmma::load_matrix_sync(a[mi], Xc + kb * PLDH + wm * 32 + mi * 16, PLDH);
#pragma unroll
                for (int ni = 0; ni < 4; ni++) {
                    wmma::fragment<wmma::matrix_b, 16, 16, 16, __half, wmma::col_major> bb;
                    wmma::load_matrix_sync(bb, Ws + (wn * 64 + ni * 16) * WLDH + kg, WLDH);
#pragma unroll
                    for (int mi = 0; mi < 2; mi++)
                        wmma::mma_sync(acc[mi][ni], a[mi], bb, acc[mi][ni]);
                }
            }
        }

        // ---- epilogue: fp32 acc -> per-warp smem stage -> fp16 g_wxh ----
        __syncthreads();   // all warps done with MMAs before stage clobbers X buffers
        {
            float* st = (float*)(smem + SM_X_OFF) + wid * 16 * STLD;   // 16x64 per warp
            __half* gph = g_wxh + (size_t)(b * NPIX + pix0 + wm * 32) * NE + wn * 64;
            const int r = lane >> 1, h = lane & 1;
#pragma unroll
            for (int mi = 0; mi < 2; mi++) {
#pragma unroll
                for (int ni = 0; ni < 4; ni++)
                    wmma::store_matrix_sync(st + ni * 16, acc[mi][ni], STLD, wmma::mem_row_major);
                __syncwarp();
                // lane -> row r (0..15), half h: convert 32 floats -> 32 halves (64B STG)
                const float2* src = (const float2*)(st + r * STLD + h * 32);
                uint4 o[4];
#pragma unroll
                for (int i = 0; i < 4; i++) {
                    uint32_t p[4];
#pragma unroll
                    for (int k = 0; k < 4; k++) {
                        float2 f = src[i * 4 + k];
                        __half2 hh = __floats2half2_rn(f.x, f.y);
                        p[k] = *(uint32_t*)&hh;
                    }
                    o[i] = make_uint4(p[0], p[1], p[2], p[3]);
                }
                uint4* dst = (uint4*)(gph + (size_t)(mi * 16 + r) * NE + h * 32);
#pragma unroll
                for (int i = 0; i < 4; i++) dst[i] = o[i];
                __syncwarp();
            }
        }
        __syncthreads();   // stage reads done before next tile's STS into Xb[0]
    }
#undef LOAD_CHUNK
}

// ===== Kernel 2: bilinear gather on fp16 Wx + bias + L2-normalize =====
static __device__ __forceinline__ void corner_acc(const __half* base, int xi, int yi,
                                                  bool valid, float wgt, int lane, float4& acc) {
    if (valid) {
        uint2 raw = ((const uint2*)(base + (size_t)(yi * 128 + xi) * NE))[lane];
        float2 f0 = __half22float2(*(__half2*)&raw.x);
        float2 f1 = __half22float2(*(__half2*)&raw.y);
        acc.x = fmaf(wgt, f0.x, acc.x);
        acc.y = fmaf(wgt, f0.y, acc.y);
        acc.z = fmaf(wgt, f1.x, acc.z);
        acc.w = fmaf(wgt, f1.y, acc.w);
    }
}

__global__ void __launch_bounds__(256) k2_sample(const float* __restrict__ kpts,
                                                 const float* __restrict__ bias,
                                                 float* __restrict__ out) {
    int gwarp = (blockIdx.x * 256 + threadIdx.x) >> 5;
    int lane = threadIdx.x & 31;
    if (gwarp >= NB * NPTS) return;
    int b = gwarp >> 12;

    float2 kp = ((const float2*)kpts)[gwarp];
    float ix = fmaf(kp.x, 64.0f, 63.5f);
    float iy = fmaf(kp.y, 64.0f, 63.5f);
    float x0f = floorf(ix), y0f = floorf(iy);
    float wx = ix - x0f, wy = iy - y0f;
    int x0 = (int)x0f, y0 = (int)y0f, x1 = x0 + 1, y1 = y0 + 1;
    float w00 = (1.f - wx) * (1.f - wy), w10 = wx * (1.f - wy);
    float w01 = (1.f - wx) * wy,         w11 = wx * wy;

    const __half* base = g_wxh + (size_t)b * NPIX * NE;
    // acc starts at 0; bias (fp32) added after gather, before normalize
    float4 acc = make_float4(0.f, 0.f, 0.f, 0.f);

    bool vx0 = (x0 >= 0) & (x0 < 128), vx1 = (x1 >= 0) & (x1 < 128);
    bool vy0 = (y0 >= 0) & (y0 < 128), vy1 = (y1 >= 0) & (y1 < 128);
    corner_acc(base, x0, y0, vx0 && vy0, w00, lane, acc);
    corner_acc(base, x1, y0, vx1 && vy0, w10, lane, acc);
    corner_acc(base, x0, y1, vx0 && vy1, w01, lane, acc);
    corner_acc(base, x1, y1, vx1 && vy1, w11, lane, acc);

    float4 bs = ((const float4*)bias)[lane];
    acc.x += bs.x; acc.y += bs.y; acc.z += bs.z; acc.w += bs.w;

    float ss = acc.x * acc.x + acc.y * acc.y + acc.z * acc.z + acc.w * acc.w;
#pragma unroll
    for (int m = 16; m > 0; m >>= 1) ss += __shfl_xor_sync(0xFFFFFFFFu, ss, m);
    float inv = 1.0f / fmaxf(sqrtf(ss), 1e-12f);
    acc.x *= inv; acc.y *= inv; acc.z *= inv; acc.w *= inv;
    ((float4*)(out + (size_t)gwarp * NE))[lane] = acc;
}

extern "C" void kernel_launch(void* const* d_in, const int* in_sizes, int n_in,
                              void* d_out, int out_size) {
    const float* x    = (const float*)d_in[0];
    const float* kpts = (const float*)d_in[1];
    const float* wmat = (const float*)d_in[2];
    const float* bias = (const float*)d_in[3];
    float* out = (float*)d_out;

    cudaFuncSetAttribute(k1_whiten, cudaFuncAttributeMaxDynamicSharedMemorySize, SM_TOT);
    k1_whiten<<<GRID1, NTHR, SM_TOT>>>(x, wmat);
    k2_sample<<<(NB * NPTS) / 8, 256>>>(kpts, bias, out);
}